// round 4
// baseline (speedup 1.0000x reference)
#include <cuda_runtime.h>
#include <cstdint>

#define NODES   64
#define NINPUT  16
#define NOUT    8
#define NEDGE   256
#define BATCH   8192
#define PASSES  64
#define G       32            // edge slots per chunk == warp size (slot = lane)
#define TB      256           // threads per block
#define CPB     8             // columns per block (1 col per warp)
#define GRIDB   (BATCH / CPB) // 1024 blocks
#define STRIDE  65            // floats per column (64 nodes + scratch row 64)
#define MAXCH   257           // provable worst case (>=1 edge/chunk) + wrap

__device__ uint2 g_recs[MAXCH * G];
__device__ int   g_nchunks;

// 64-bit inclusive OR-scan across the warp
__device__ __forceinline__ unsigned long long orscan_incl(unsigned long long x,
                                                          int lane) {
    #pragma unroll
    for (int o = 1; o < 32; o <<= 1) {
        unsigned lo = __shfl_up_sync(0xffffffffu, (unsigned)x, o);
        unsigned hi = __shfl_up_sync(0xffffffffu, (unsigned)(x >> 32), o);
        unsigned long long y = ((unsigned long long)hi << 32) | lo;
        if (lane >= o) x |= y;
    }
    return x;
}

// ---------------------------------------------------------------------------
// Warp-parallel greedy list scheduler. Chunks of up to G=32 pairwise
// hazard-free edges; each accepted edge is conflict-checked against the
// OR-scan footprint of ALL earlier-in-program-order remaining edges
// (preserves RAW/WAW/WAR of the sequential reference).
// rec.x = (dst_byte_off << 16) | src_byte_off, rec.y = w * 2*log2(e).
// ---------------------------------------------------------------------------
__global__ void sched_kernel(const float* __restrict__ wght,
                             const int*   __restrict__ src,
                             const int*   __restrict__ dst) {
    __shared__ int   ss[NEDGE], sd[NEDGE];
    __shared__ float sw[NEDGE];
    __shared__ short rlist[NEDGE], tmpl[NEDGE];
    __shared__ unsigned char accf[NEDGE];
    const int lane = threadIdx.x;
    const float K2 = 2.8853900817779268f;  // 2 * log2(e)

    for (int e = lane; e < NEDGE; e += 32) {
        ss[e] = src[e]; sd[e] = dst[e]; sw[e] = wght[e] * K2;
        rlist[e] = (short)e;
    }
    __syncwarp();

    const unsigned ltmask = (1u << lane) - 1u;
    uint2 dummy; dummy.x = (256u << 16) | 256u; dummy.y = __float_as_uint(0.0f);

    int nrem = NEDGE, nch = 0;
    while (nrem > 0) {
        unsigned long long Wm = 0ull, Rm = 0ull;
        int members = 0;
        for (int base = 0; base < nrem && members < G; base += 32) {
            const int  idx   = base + lane;
            const bool valid = idx < nrem;
            const int  e = valid ? rlist[idx] : 0;
            const int  s = ss[e], d = sd[e];
            const unsigned long long myW = valid ? (1ull << d) : 0ull;
            const unsigned long long myR = valid ? (1ull << s) : 0ull;
            const unsigned long long iW = orscan_incl(myW, lane);
            const unsigned long long iR = orscan_incl(myR, lane);
            // exclusive = shfl_up(incl, 1)
            unsigned lo = __shfl_up_sync(0xffffffffu, (unsigned)iW, 1);
            unsigned hi = __shfl_up_sync(0xffffffffu, (unsigned)(iW >> 32), 1);
            const unsigned long long eW =
                (lane == 0) ? 0ull : (((unsigned long long)hi << 32) | lo);
            lo = __shfl_up_sync(0xffffffffu, (unsigned)iR, 1);
            hi = __shfl_up_sync(0xffffffffu, (unsigned)(iR >> 32), 1);
            const unsigned long long eR =
                (lane == 0) ? 0ull : (((unsigned long long)hi << 32) | lo);

            const unsigned long long tW = Wm | eW;
            const unsigned long long tR = Rm | eR;
            const bool ok = valid &&
                            !((tW >> s) & 1ull) && !((tW >> d) & 1ull) &&
                            !((tR >> d) & 1ull);
            const unsigned bal  = __ballot_sync(0xffffffffu, ok);
            const int      rank = members + __popc(bal & ltmask);
            const bool accept = ok && (rank < G);
            if (accept) {
                uint2 rec;
                rec.x = ((unsigned)(d * 4) << 16) | (unsigned)(s * 4);
                rec.y = __float_as_uint(sw[e]);
                g_recs[nch * G + rank] = rec;
            }
            if (valid) accf[idx] = accept ? 1 : 0;
            members += __popc(__ballot_sync(0xffffffffu, accept));
            // carry footprint of everything scanned (matters only if we
            // continue scanning this chunk)
            lo = __shfl_sync(0xffffffffu, (unsigned)iW, 31);
            hi = __shfl_sync(0xffffffffu, (unsigned)(iW >> 32), 31);
            Wm |= ((unsigned long long)hi << 32) | lo;
            lo = __shfl_sync(0xffffffffu, (unsigned)iR, 31);
            hi = __shfl_sync(0xffffffffu, (unsigned)(iR >> 32), 31);
            Rm |= ((unsigned long long)hi << 32) | lo;
        }
        // pad unused slots
        if (lane >= members) g_recs[nch * G + lane] = dummy;
        // compact remaining list (order preserved)
        int wrpos = 0;
        for (int base = 0; base < nrem; base += 32) {
            const int  idx   = base + lane;
            const bool valid = idx < nrem;
            const int  e     = valid ? rlist[idx] : 0;
            const bool keep  = valid && !accf[idx];
            const unsigned kb = __ballot_sync(0xffffffffu, keep);
            if (keep) tmpl[wrpos + __popc(kb & ltmask)] = (short)e;
            wrpos += __popc(kb);
        }
        __syncwarp();
        for (int i = lane; i < wrpos; i += 32) rlist[i] = tmpl[i];
        __syncwarp();
        nrem = wrpos;
        nch++;
    }
    // wrap chunk = copy of chunk 0 (for prefetch wrap-around)
    g_recs[nch * G + lane] = g_recs[lane];
    if (lane == 0) g_nchunks = nch;
}

// ---------------------------------------------------------------------------
// Main kernel: 1 column per warp, 32 edge slots per chunk (slot = lane).
// Node state [col][row] in smem, stride 65 (bank = (col+row) mod 32; max
// 2-way conflicts since rows span 0..64). __syncwarp() orders smem between
// chunks. tanh(x) = 1 - 2/(exp2(x*2log2e)+1) via MUFU ex2/rcp.
// ---------------------------------------------------------------------------
__global__ void __launch_bounds__(TB, 1)
net_kernel(const float* __restrict__ x, float* __restrict__ out) {
    __shared__ float vals[CPB * STRIDE];

    const int tid  = threadIdx.x;
    const int lane = tid & 31;
    const int wid  = tid >> 5;          // local column 0..7
    const int bc   = blockIdx.x * CPB;

    for (int i = tid; i < CPB * NINPUT; i += TB) {
        const int r = i >> 3, c = i & 7;
        vals[c * STRIDE + r] = x[r * BATCH + bc + c];
    }
    for (int i = tid; i < CPB * (STRIDE - NINPUT); i += TB) {
        const int r = NINPUT + (i >> 3), c = i & 7;
        vals[c * STRIDE + r] = 0.0f;
    }
    __syncthreads();

    const int nch = g_nchunks;
    char* base = (char*)(vals + wid * STRIDE);

    uint2 rec = __ldg(&g_recs[lane]);
    #pragma unroll 1
    for (int p = 0; p < PASSES; p++) {
        #pragma unroll 2
        for (int c = 0; c < nch; c++) {
            const uint2 nxt = __ldg(&g_recs[(c + 1) * G + lane]);  // wrap=chunk0
            const unsigned sb = rec.x & 0xffffu;
            const unsigned db = rec.x >> 16;
            const float wv = __uint_as_float(rec.y);
            const float v  = *(const float*)(base + sb);
            const float t1 = *(const float*)(base + db) + 1.0f;
            const float a = v * wv;
            float ev;  asm("ex2.approx.f32 %0, %1;" : "=f"(ev) : "f"(a));
            float r2;  asm("rcp.approx.f32 %0, %1;" : "=f"(r2) : "f"(ev + 1.0f));
            *(float*)(base + db) = fmaf(-2.0f, r2, t1);  // pv + 1 - 2/(ev+1)
            rec = nxt;
            __syncwarp();
        }
    }
    __syncthreads();

    for (int i = tid; i < CPB * NOUT; i += TB) {
        const int r = i >> 3, c = i & 7;
        out[r * BATCH + bc + c] = tanhf(vals[c * STRIDE + NINPUT + r]);
    }
}

extern "C" void kernel_launch(void* const* d_in, const int* in_sizes, int n_in,
                              void* d_out, int out_size) {
    const float* x   = (const float*)d_in[0];
    const float* w   = (const float*)d_in[1];
    const int*   src = (const int*)d_in[2];
    const int*   dst = (const int*)d_in[3];
    (void)in_sizes; (void)n_in; (void)out_size;

    sched_kernel<<<1, 32>>>(w, src, dst);
    net_kernel<<<GRIDB, TB>>>(x, (float*)d_out);
}

// round 6
// speedup vs baseline: 1.7763x; 1.7763x over previous
#include <cuda_runtime.h>
#include <cstdint>

#define NODES   64
#define NINPUT  16
#define NOUT    8
#define NEDGE   256
#define BATCH   8192
#define PASSES  64
#define G       16            // edge slots per chunk (lanes per column)
#define TB      128           // threads per block
#define CPB     8             // columns per block (2 cols per warp)
#define GRIDB   (BATCH / CPB) // 1024 blocks
#define STRIDE  65            // floats per column (64 nodes + scratch row 64)
#define MAXCH   257           // worst case chunks + wrap chunk

__device__ uint2 g_recs[MAXCH * G + G];
__device__ int   g_nchunks;

// 64-bit inclusive OR-scan across the warp
__device__ __forceinline__ unsigned long long orscan_incl(unsigned long long x,
                                                          int lane) {
    #pragma unroll
    for (int o = 1; o < 32; o <<= 1) {
        unsigned lo = __shfl_up_sync(0xffffffffu, (unsigned)x, o);
        unsigned hi = __shfl_up_sync(0xffffffffu, (unsigned)(x >> 32), o);
        unsigned long long y = ((unsigned long long)hi << 32) | lo;
        if (lane >= o) x |= y;
    }
    return x;
}

__device__ __forceinline__ unsigned long long bcast64(unsigned long long x,
                                                      int srclane) {
    unsigned lo = __shfl_sync(0xffffffffu, (unsigned)x, srclane);
    unsigned hi = __shfl_sync(0xffffffffu, (unsigned)(x >> 32), srclane);
    return ((unsigned long long)hi << 32) | lo;
}

// ---------------------------------------------------------------------------
// Warp-parallel greedy list scheduler with exact dependence rules for a
// sum-accumulation graph:
//   - RAW: candidate src not written by any earlier remaining edge/member
//   - WAR: candidate dst not read by any earlier remaining edge/member
//   - in-chunk WAW race: member dsts pairwise distinct
//   - WAW across chunks: unordered (fp adds commute; reassociation only --
//     every read still sees exactly its program-order set of terms)
// accf[] is zero-filled for ALL remaining positions at the start of every
// chunk (the scan may early-exit once the chunk is full; compaction must not
// see stale flags -- this was the R5 corruption).
// rec.x = (dst_byte_off << 16) | src_byte_off, rec.y = w * 2*log2(e).
// ---------------------------------------------------------------------------
__global__ void sched_kernel(const float* __restrict__ wght,
                             const int*   __restrict__ src,
                             const int*   __restrict__ dst) {
    __shared__ int   ss[NEDGE], sd[NEDGE];
    __shared__ float sw[NEDGE];
    __shared__ short rlist[NEDGE], tmpl[NEDGE];
    __shared__ unsigned char accf[NEDGE];
    const int lane = threadIdx.x;
    const float K2 = 2.8853900817779268f;  // 2 * log2(e)

    for (int e = lane; e < NEDGE; e += 32) {
        ss[e] = src[e]; sd[e] = dst[e]; sw[e] = wght[e] * K2;
        rlist[e] = (short)e;
    }
    __syncwarp();

    const unsigned ltmask = (1u << lane) - 1u;
    uint2 dummy; dummy.x = (256u << 16) | 256u;  // scratch row 64
    dummy.y = __float_as_uint(0.0f);             // tanh(0)=0 -> no-op

    int nrem = NEDGE, nch = 0;
    while (nrem > 0) {
        // CRITICAL: clear accept flags for every remaining position before
        // the (possibly early-exiting) scan; compaction reads all of them.
        for (int i = lane; i < nrem; i += 32) accf[i] = 0;
        __syncwarp();

        unsigned long long Wall = 0ull, Rall = 0ull, Wmem = 0ull;
        int members = 0;
        for (int base = 0; base < nrem && members < G; base += 32) {
            const int  idx   = base + lane;
            const bool valid = idx < nrem;
            const int  e = valid ? rlist[idx] : 0;
            const int  s = ss[e], d = sd[e];
            const unsigned long long myW = valid ? (1ull << d) : 0ull;
            const unsigned long long myR = valid ? (1ull << s) : 0ull;
            const unsigned long long iW = orscan_incl(myW, lane);
            const unsigned long long iR = orscan_incl(myR, lane);
            unsigned lo = __shfl_up_sync(0xffffffffu, (unsigned)iW, 1);
            unsigned hi = __shfl_up_sync(0xffffffffu, (unsigned)(iW >> 32), 1);
            const unsigned long long eW =
                (lane == 0) ? 0ull : (((unsigned long long)hi << 32) | lo);
            lo = __shfl_up_sync(0xffffffffu, (unsigned)iR, 1);
            hi = __shfl_up_sync(0xffffffffu, (unsigned)(iR >> 32), 1);
            const unsigned long long eR =
                (lane == 0) ? 0ull : (((unsigned long long)hi << 32) | lo);

            const unsigned long long tWall = Wall | eW;  // excl scan, all W
            const unsigned long long tRall = Rall | eR;  // excl scan, all R
            const bool ok0 = valid &&
                             !((tWall >> s) & 1ull) &&
                             !((tRall >> d) & 1ull) &&
                             !((Wmem  >> d) & 1ull);
            // intra-batch member-dst dedup (keep lowest ok0 lane per dst)
            const unsigned peers = __match_any_sync(0xffffffffu, d);
            const unsigned bal0  = __ballot_sync(0xffffffffu, ok0);
            const bool ok = ok0 && ((peers & bal0 & ltmask) == 0u);
            const unsigned bal  = __ballot_sync(0xffffffffu, ok);
            const int      rank = members + __popc(bal & ltmask);
            const bool accept = ok && (rank < G);
            if (accept) {
                uint2 rec;
                rec.x = ((unsigned)(d * 4) << 16) | (unsigned)(s * 4);
                rec.y = __float_as_uint(sw[e]);
                g_recs[nch * G + rank] = rec;
            }
            if (accept) accf[idx] = 1;
            members += __popc(__ballot_sync(0xffffffffu, accept));
            // fold this batch's total footprint into the carried masks
            Wall |= bcast64(iW, 31);
            Rall |= bcast64(iR, 31);
            const unsigned accWlo = __reduce_or_sync(0xffffffffu,
                accept ? (unsigned)(1ull << d) : 0u);
            const unsigned accWhi = __reduce_or_sync(0xffffffffu,
                accept ? (unsigned)((1ull << d) >> 32) : 0u);
            Wmem |= ((unsigned long long)accWhi << 32) | accWlo;
        }
        if (lane >= members && lane < G) g_recs[nch * G + lane] = dummy;
        // compact remaining list (program order preserved)
        int wrpos = 0;
        for (int base = 0; base < nrem; base += 32) {
            const int  idx   = base + lane;
            const bool valid = idx < nrem;
            const int  e     = valid ? rlist[idx] : 0;
            const bool keep  = valid && !accf[idx];
            const unsigned kb = __ballot_sync(0xffffffffu, keep);
            if (keep) tmpl[wrpos + __popc(kb & ltmask)] = (short)e;
            wrpos += __popc(kb);
        }
        __syncwarp();
        for (int i = lane; i < wrpos; i += 32) rlist[i] = tmpl[i];
        __syncwarp();
        nrem = wrpos;
        nch++;
    }
    // wrap chunk = copy of chunk 0 (prefetch wrap-around)
    if (lane < G) g_recs[nch * G + lane] = g_recs[lane];
    if (lane == 0) g_nchunks = nch;
}

// ---------------------------------------------------------------------------
// Main kernel (R3 layout, best measured): warp = 2 columns x 16 edge slots.
// Node state [col][row] in smem, stride 65 floats. __syncwarp() orders smem
// between chunks. tanh(x) = 1 - 2/(exp2(x*2log2e)+1) via MUFU ex2/rcp.
// ---------------------------------------------------------------------------
__global__ void __launch_bounds__(TB, 1)
net_kernel(const float* __restrict__ x, float* __restrict__ out) {
    __shared__ float vals[CPB * STRIDE];

    const int tid  = threadIdx.x;
    const int lane = tid & 31;
    const int wid  = tid >> 5;
    const int cl   = wid * 2 + (lane >> 4);  // local column 0..7
    const int slot = lane & 15;
    const int bc   = blockIdx.x * CPB;

    for (int i = tid; i < CPB * NINPUT; i += TB) {
        const int r = i >> 3, c = i & 7;
        vals[c * STRIDE + r] = x[r * BATCH + bc + c];
    }
    for (int i = tid; i < CPB * (STRIDE - NINPUT); i += TB) {
        const int r = NINPUT + (i >> 3), c = i & 7;
        vals[c * STRIDE + r] = 0.0f;
    }
    __syncthreads();

    const int nch = g_nchunks;
    char* base = (char*)(vals + cl * STRIDE);

    uint2 rec = __ldg(&g_recs[slot]);
    #pragma unroll 1
    for (int p = 0; p < PASSES; p++) {
        #pragma unroll 2
        for (int c = 0; c < nch; c++) {
            const uint2 nxt = __ldg(&g_recs[(c + 1) * G + slot]);  // wrap=chunk0
            const unsigned sb = rec.x & 0xffffu;
            const unsigned db = rec.x >> 16;
            const float wv = __uint_as_float(rec.y);
            const float v  = *(const float*)(base + sb);
            const float t1 = *(const float*)(base + db) + 1.0f;
            const float a = v * wv;
            float ev;  asm("ex2.approx.f32 %0, %1;" : "=f"(ev) : "f"(a));
            float r2;  asm("rcp.approx.f32 %0, %1;" : "=f"(r2) : "f"(ev + 1.0f));
            *(float*)(base + db) = fmaf(-2.0f, r2, t1);  // pv + 1 - 2/(ev+1)
            rec = nxt;
            __syncwarp();
        }
    }
    __syncthreads();

    for (int i = tid; i < CPB * NOUT; i += TB) {
        const int r = i >> 3, c = i & 7;
        out[r * BATCH + bc + c] = tanhf(vals[c * STRIDE + NINPUT + r]);
    }
}

extern "C" void kernel_launch(void* const* d_in, const int* in_sizes, int n_in,
                              void* d_out, int out_size) {
    const float* x   = (const float*)d_in[0];
    const float* w   = (const float*)d_in[1];
    const int*   src = (const int*)d_in[2];
    const int*   dst = (const int*)d_in[3];
    (void)in_sizes; (void)n_in; (void)out_size;

    sched_kernel<<<1, 32>>>(w, src, dst);
    net_kernel<<<GRIDB, TB>>>(x, (float*)d_out);
}